// round 6
// baseline (speedup 1.0000x reference)
#include <cuda_runtime.h>
#include <cstdint>

#define BS_ROWS     1024                      // B*S
#define VOCAB       50257
#define DMODEL      768
#define D4          (DMODEL / 4)              // 192 float4 per row
#define TOTAL_ELEMS (BS_ROWS * (long long)VOCAB)   // 51,463,168
#define TOTAL_F4    12865792u                 // 256 * 50257
#define NTHREADS    256
#define NBLOCKS     2960                      // 148 SMs * 5 blocks/SM * 4 waves
#define STRIDE      (NBLOCKS * NTHREADS)      // 757,760  (~17.0 f4/thread)

// ---------------------------------------------------------------------------
// Record one nonzero into the block's shared buffer (rare: 1024 total events).
// ---------------------------------------------------------------------------
__device__ __forceinline__ void record4(uint4 v, unsigned i,
                                        int* s_cnt, int* s_g, float* s_v)
{
    if (v.x | v.y | v.z | v.w) {                       // almost never taken
        unsigned base = i * 4u;
        float f[4] = { __uint_as_float(v.x), __uint_as_float(v.y),
                       __uint_as_float(v.z), __uint_as_float(v.w) };
        #pragma unroll
        for (int k = 0; k < 4; k++) {
            if (f[k] != 0.0f) {
                int slot = atomicAdd(s_cnt, 1);
                s_g[slot] = (int)(base + k);           // < 2^26, fits int
                s_v[slot] = f[k];
            }
        }
    }
}

// ---------------------------------------------------------------------------
// Fused kernel: 4-exact-wave scan + deferred block-level emission.
// ---------------------------------------------------------------------------
__global__ void __launch_bounds__(NTHREADS, 5)
fused_embed_kernel(const uint4* __restrict__ oh4,
                   const float4* __restrict__ w4,
                   float4* __restrict__ out4)
{
    __shared__ int   s_cnt;
    __shared__ int   s_g[BS_ROWS];
    __shared__ float s_v[BS_ROWS];

    if (threadIdx.x == 0) s_cnt = 0;
    __syncthreads();

    unsigned i = blockIdx.x * NTHREADS + threadIdx.x;

    // ---- phase 1: scan. ~17 f4/thread = 2 x batch-8 + 1 single ----
    while (i + 7u * STRIDE < TOTAL_F4) {
        uint4 v[8];
        #pragma unroll
        for (int u = 0; u < 8; u++) v[u] = __ldg(&oh4[i + u * STRIDE]);
        #pragma unroll
        for (int u = 0; u < 8; u++)
            record4(v[u], i + u * STRIDE, &s_cnt, s_g, s_v);
        i += 8u * STRIDE;
    }
    while (i < TOTAL_F4) {
        uint4 v = __ldg(&oh4[i]);
        record4(v, i, &s_cnt, s_g, s_v);
        i += STRIDE;
    }

    // ---- phase 2: block-cooperative emission ----
    __syncthreads();
    const int cnt = s_cnt;
    const int t   = threadIdx.x;
    for (int e = 0; e < cnt; e++) {
        unsigned g = (unsigned)s_g[e];
        float    v = s_v[e];
        int row = (int)(g / VOCAB);
        int col = (int)(g - (unsigned)row * VOCAB);
        if (t < D4) {                                  // 192 of 256 threads
            float4 w = __ldg(&w4[col * D4 + t]);
            w.x *= v; w.y *= v; w.z *= v; w.w *= v;
            out4[row * D4 + t] = w;
        }
    }
}

// ---------------------------------------------------------------------------
extern "C" void kernel_launch(void* const* d_in, const int* in_sizes, int n_in,
                              void* d_out, int out_size)
{
    const float* one_hot = nullptr;
    const float* weight  = nullptr;
    for (int i = 0; i < n_in; i++) {
        if (in_sizes[i] == (int)TOTAL_ELEMS)     one_hot = (const float*)d_in[i];
        else if (in_sizes[i] == VOCAB * DMODEL)  weight  = (const float*)d_in[i];
    }

    fused_embed_kernel<<<NBLOCKS, NTHREADS>>>((const uint4*)one_hot,
                                              (const float4*)weight,
                                              (float4*)d_out);
}

// round 7
// speedup vs baseline: 1.0009x; 1.0009x over previous
#include <cuda_runtime.h>
#include <cstdint>

#define BS_ROWS     1024                      // B*S
#define VOCAB       50257
#define DMODEL      768
#define D4          (DMODEL / 4)              // 192 float4 per row
#define TOTAL_ELEMS (BS_ROWS * (long long)VOCAB)   // 51,463,168
#define TOTAL_F4    12865792u                 // 256 * 50257
#define NTHREADS    256
#define NBLOCKS     888                       // 148 SMs x 6 blocks/SM = one wave
#define NTOTAL      (NBLOCKS * NTHREADS)      // 227,328 threads
#define NCHUNK      (TOTAL_F4 / 4u)           // 3,216,448 chunks of 4 f4
#define FULLIT      14                        // 14 * NTOTAL = 3,182,592 chunks

// ---------------------------------------------------------------------------
// Record one nonzero into the block's shared buffer (rare: 1024 total events).
// i = float4 index; element index i*4+k < 2^26 fits int.
// ---------------------------------------------------------------------------
__device__ __forceinline__ void record4(uint4 v, unsigned i,
                                        int* s_cnt, int* s_g, float* s_v)
{
    if (v.x | v.y | v.z | v.w) {                       // almost never taken
        unsigned base = i * 4u;
        float f[4] = { __uint_as_float(v.x), __uint_as_float(v.y),
                       __uint_as_float(v.z), __uint_as_float(v.w) };
        #pragma unroll
        for (int k = 0; k < 4; k++) {
            if (f[k] != 0.0f) {
                int slot = atomicAdd(s_cnt, 1);
                s_g[slot] = (int)(base + k);
                s_v[slot] = f[k];
            }
        }
    }
}

// ---------------------------------------------------------------------------
// Fused kernel: contiguous-chunk scan (64 B/thread/iter, one-wave persistent)
// + deferred block-level emission.
// ---------------------------------------------------------------------------
__global__ void __launch_bounds__(NTHREADS, 6)
fused_embed_kernel(const uint4* __restrict__ oh4,
                   const float4* __restrict__ w4,
                   float4* __restrict__ out4)
{
    __shared__ int   s_cnt;
    __shared__ int   s_g[BS_ROWS];
    __shared__ float s_v[BS_ROWS];

    if (threadIdx.x == 0) s_cnt = 0;
    __syncthreads();

    unsigned c = blockIdx.x * NTHREADS + threadIdx.x;  // chunk id

    // ---- phase 1: scan. Each chunk = 4 consecutive float4s (64 B). ----
    #pragma unroll 1
    for (int it = 0; it < FULLIT; ++it, c += NTOTAL) {
        const uint4* p = oh4 + (size_t)c * 4u;
        uint4 v0 = __ldcs(p + 0);
        uint4 v1 = __ldcs(p + 1);
        uint4 v2 = __ldcs(p + 2);
        uint4 v3 = __ldcs(p + 3);
        unsigned b = c * 4u;
        record4(v0, b + 0, &s_cnt, s_g, s_v);
        record4(v1, b + 1, &s_cnt, s_g, s_v);
        record4(v2, b + 2, &s_cnt, s_g, s_v);
        record4(v3, b + 3, &s_cnt, s_g, s_v);
    }
    // partial 15th chunk-iteration for the first 33,856 threads
    if (c < NCHUNK) {
        const uint4* p = oh4 + (size_t)c * 4u;
        uint4 v0 = __ldcs(p + 0);
        uint4 v1 = __ldcs(p + 1);
        uint4 v2 = __ldcs(p + 2);
        uint4 v3 = __ldcs(p + 3);
        unsigned b = c * 4u;
        record4(v0, b + 0, &s_cnt, s_g, s_v);
        record4(v1, b + 1, &s_cnt, s_g, s_v);
        record4(v2, b + 2, &s_cnt, s_g, s_v);
        record4(v3, b + 3, &s_cnt, s_g, s_v);
    }

    // ---- phase 2: block-cooperative emission ----
    __syncthreads();
    const int cnt = s_cnt;
    const int t   = threadIdx.x;
    for (int e = 0; e < cnt; e++) {
        unsigned g = (unsigned)s_g[e];
        float    v = s_v[e];
        int row = (int)(g / VOCAB);
        int col = (int)(g - (unsigned)row * VOCAB);
        if (t < D4) {
            float4 w = __ldg(&w4[col * D4 + t]);
            w.x *= v; w.y *= v; w.z *= v; w.w *= v;
            out4[row * D4 + t] = w;
        }
    }
}

// ---------------------------------------------------------------------------
extern "C" void kernel_launch(void* const* d_in, const int* in_sizes, int n_in,
                              void* d_out, int out_size)
{
    const float* one_hot = nullptr;
    const float* weight  = nullptr;
    for (int i = 0; i < n_in; i++) {
        if (in_sizes[i] == (int)TOTAL_ELEMS)     one_hot = (const float*)d_in[i];
        else if (in_sizes[i] == VOCAB * DMODEL)  weight  = (const float*)d_in[i];
    }

    fused_embed_kernel<<<NBLOCKS, NTHREADS>>>((const uint4*)one_hot,
                                              (const float4*)weight,
                                              (float4*)d_out);
}

// round 8
// speedup vs baseline: 1.0580x; 1.0571x over previous
#include <cuda_runtime.h>
#include <cstdint>

#define BS_ROWS     1024                      // B*S
#define VOCAB       50257
#define DMODEL      768
#define D4          (DMODEL / 4)              // 192 float4 per row
#define TOTAL_ELEMS (BS_ROWS * (long long)VOCAB)   // 51,463,168
#define TOTAL_F4    12865792u                 // 256 * 50257
#define NTHREADS    256
#define NBLOCKS     2960                      // 148 SMs * 5 blocks/SM * 4 waves
#define STRIDE      (NBLOCKS * NTHREADS)      // 757,760  (~17.0 f4/thread)

// ---------------------------------------------------------------------------
// Record one nonzero into the block's shared buffer (rare: 1024 total events).
// ---------------------------------------------------------------------------
__device__ __forceinline__ void record4(uint4 v, unsigned i,
                                        int* s_cnt, int* s_g, float* s_v)
{
    if (v.x | v.y | v.z | v.w) {                       // almost never taken
        unsigned base = i * 4u;
        float f[4] = { __uint_as_float(v.x), __uint_as_float(v.y),
                       __uint_as_float(v.z), __uint_as_float(v.w) };
        #pragma unroll
        for (int k = 0; k < 4; k++) {
            if (f[k] != 0.0f) {
                int slot = atomicAdd(s_cnt, 1);
                s_g[slot] = (int)(base + k);           // < 2^26, fits int
                s_v[slot] = f[k];
            }
        }
    }
}

// ---------------------------------------------------------------------------
// Fused kernel: R6 strided batch-8 scan (best measured: 6.14 TB/s) with
// evict-first streaming loads + deferred block-level emission.
// ---------------------------------------------------------------------------
__global__ void __launch_bounds__(NTHREADS, 5)
fused_embed_kernel(const uint4* __restrict__ oh4,
                   const float4* __restrict__ w4,
                   float4* __restrict__ out4)
{
    __shared__ int   s_cnt;
    __shared__ int   s_g[BS_ROWS];
    __shared__ float s_v[BS_ROWS];

    if (threadIdx.x == 0) s_cnt = 0;
    __syncthreads();

    unsigned i = blockIdx.x * NTHREADS + threadIdx.x;

    // ---- phase 1: scan. ~17 f4/thread = 2 x batch-8 + 1 single ----
    while (i + 7u * STRIDE < TOTAL_F4) {
        uint4 v[8];
        #pragma unroll
        for (int u = 0; u < 8; u++) v[u] = __ldcs(&oh4[i + u * STRIDE]);
        #pragma unroll
        for (int u = 0; u < 8; u++)
            record4(v[u], i + u * STRIDE, &s_cnt, s_g, s_v);
        i += 8u * STRIDE;
    }
    while (i < TOTAL_F4) {
        uint4 v = __ldcs(&oh4[i]);
        record4(v, i, &s_cnt, s_g, s_v);
        i += STRIDE;
    }

    // ---- phase 2: block-cooperative emission ----
    __syncthreads();
    const int cnt = s_cnt;
    const int t   = threadIdx.x;
    for (int e = 0; e < cnt; e++) {
        unsigned g = (unsigned)s_g[e];
        float    v = s_v[e];
        int row = (int)(g / VOCAB);
        int col = (int)(g - (unsigned)row * VOCAB);
        if (t < D4) {                                  // 192 of 256 threads
            float4 w = __ldg(&w4[col * D4 + t]);
            w.x *= v; w.y *= v; w.z *= v; w.w *= v;
            out4[row * D4 + t] = w;
        }
    }
}

// ---------------------------------------------------------------------------
extern "C" void kernel_launch(void* const* d_in, const int* in_sizes, int n_in,
                              void* d_out, int out_size)
{
    const float* one_hot = nullptr;
    const float* weight  = nullptr;
    for (int i = 0; i < n_in; i++) {
        if (in_sizes[i] == (int)TOTAL_ELEMS)     one_hot = (const float*)d_in[i];
        else if (in_sizes[i] == VOCAB * DMODEL)  weight  = (const float*)d_in[i];
    }

    fused_embed_kernel<<<NBLOCKS, NTHREADS>>>((const uint4*)one_hot,
                                              (const float4*)weight,
                                              (float4*)d_out);
}

// round 9
// speedup vs baseline: 1.5052x; 1.4227x over previous
#include <cuda_runtime.h>
#include <cstdint>

#define BS_ROWS     1024                      // B*S  (one block per row)
#define VOCAB       50257
#define DMODEL      768
#define D4          (DMODEL / 4)              // 192 float4 per row
#define TOTAL_ELEMS (BS_ROWS * (long long)VOCAB)   // 51,463,168
#define NTHREADS    256
#define CHUNK_F4    (NTHREADS * 4)            // 1024 float4 = 16 KB per chunk

// ---------------------------------------------------------------------------
// One block per (b,s) row. Scan the row in 16 KB chunks; once the row's
// single nonzero is found, stop reading and emit out[row,:] = v*weight[col,:].
// Expected traffic: ~52% of the one-hot tensor instead of 100%.
// ---------------------------------------------------------------------------
__global__ void __launch_bounds__(NTHREADS, 8)
row_scan_embed_kernel(const uint4* __restrict__ oh4,
                      const float4* __restrict__ w4,
                      float4* __restrict__ out4)
{
    __shared__ int   s_found;
    __shared__ int   s_col;
    __shared__ float s_val;

    const unsigned row = blockIdx.x;
    const int      t   = threadIdx.x;

    if (t == 0) s_found = 0;
    __syncthreads();

    // Element range of this row, and the covering aligned float4 range.
    const unsigned rowbeg = row * (unsigned)VOCAB;
    const unsigned rowend = rowbeg + (unsigned)VOCAB;
    const unsigned s4     = rowbeg >> 2;                 // floor
    const unsigned e4     = (rowend + 3u) >> 2;          // ceil

    for (unsigned base = s4; base < e4; base += CHUNK_F4) {
        const unsigned i0 = base + (unsigned)t;

        // load up to 4 float4s (coalesced, guarded at the row's end)
        uint4 v[4];
        #pragma unroll
        for (int u = 0; u < 4; u++) {
            unsigned idx = i0 + u * (unsigned)NTHREADS;
            v[u] = (idx < e4) ? __ldcs(&oh4[idx]) : make_uint4(0, 0, 0, 0);
        }

        // rare path: record the nonzero if it belongs to THIS row
        #pragma unroll
        for (int u = 0; u < 4; u++) {
            if (v[u].x | v[u].y | v[u].z | v[u].w) {
                unsigned gb = (i0 + u * (unsigned)NTHREADS) * 4u;
                float f[4] = { __uint_as_float(v[u].x), __uint_as_float(v[u].y),
                               __uint_as_float(v[u].z), __uint_as_float(v[u].w) };
                #pragma unroll
                for (int k = 0; k < 4; k++) {
                    unsigned g = gb + k;
                    if (f[k] != 0.0f && g >= rowbeg && g < rowend) {
                        s_col   = (int)(g - rowbeg);
                        s_val   = f[k];
                        s_found = 1;          // exactly one writer per row
                    }
                }
            }
        }

        // uniform early-exit decision (double barrier: read-then-fence)
        __syncthreads();
        int f = s_found;
        __syncthreads();
        if (f) break;
    }

    // ---- emit: out[row,:] = val * weight[col,:] (192 threads) ----
    if (t < D4) {
        const int   col = s_col;
        const float vv  = s_val;
        float4 w = __ldg(&w4[(unsigned)col * D4 + t]);
        w.x *= vv; w.y *= vv; w.z *= vv; w.w *= vv;
        out4[row * D4 + t] = w;
    }
}

// ---------------------------------------------------------------------------
extern "C" void kernel_launch(void* const* d_in, const int* in_sizes, int n_in,
                              void* d_out, int out_size)
{
    const float* one_hot = nullptr;
    const float* weight  = nullptr;
    for (int i = 0; i < n_in; i++) {
        if (in_sizes[i] == (int)TOTAL_ELEMS)     one_hot = (const float*)d_in[i];
        else if (in_sizes[i] == VOCAB * DMODEL)  weight  = (const float*)d_in[i];
    }

    row_scan_embed_kernel<<<BS_ROWS, NTHREADS>>>((const uint4*)one_hot,
                                                 (const float4*)weight,
                                                 (float4*)d_out);
}